// round 7
// baseline (speedup 1.0000x reference)
#include <cuda_runtime.h>

// QueryEncDec: 2x128-layer scalar GRU (H=in=1), T=256, fused 256-layer wavefront.
// TWO layers per thread (128 threads, 4 warps): one __shfl_up per 2 GRU cells;
// the intra-thread layer pair chains in registers. Warp boundaries: write-once
// smem buffers + named-barrier producer/consumer sync per 8-step chunk.
// All gates via tanh.approx.
//
// out[0:256]   = dec_out  (layer 255 output at each t)
// out[256:384] = dec_h    (final hidden of global layers 128..255)

#define GRU_T 256
#define NW    4
#define KC    8
#define NCH   36     // 36*8 = 288 >= 287 inner steps

__device__ __forceinline__ float ftanh(float a) {
    float r; asm("tanh.approx.f32 %0, %1;" : "=f"(r) : "f"(a)); return r;
}

__global__ __launch_bounds__(128, 1)
void gru_wave_v7(const float* __restrict__ X,
                 const float* __restrict__ ewi, const float* __restrict__ ewh,
                 const float* __restrict__ ebi, const float* __restrict__ ebh,
                 const float* __restrict__ dwi, const float* __restrict__ dwh,
                 const float* __restrict__ dbi, const float* __restrict__ dbh,
                 float* __restrict__ out)
{
    const int tid  = threadIdx.x;      // 0..127
    const int w    = tid >> 5;
    const int lane = tid & 31;
    const int la   = 2 * tid;          // first owned global layer
    const int lb   = la + 1;           // second owned global layer

    __shared__ __align__(16) float xs[GRU_T];
    __shared__ __align__(16) float bb[NW - 1][GRU_T];   // boundary outputs
    __shared__ int rel_scratch[NW];

    if (tid < 128) { xs[tid] = X[tid]; xs[tid + 128] = X[tid + 128]; }

    // fetch per-layer weights (torch gate order r,z,n) for a layer index
    auto loadw = [&](int l, float& hwi_r, float& hwh_r, float& hb_r,
                     float& hwi_z, float& hwh_z, float& hb_z,
                     float& wi_n_, float& bi_n_, float& hwh_n, float& hbh_n) {
        const bool enc = (l < 128);
        const int  li  = enc ? l : (l - 128);
        const float* wi = enc ? ewi : dwi;
        const float* wh = enc ? ewh : dwh;
        const float* bi = enc ? ebi : dbi;
        const float* bh = enc ? ebh : dbh;
        const float wi_r = wi[li*3+0], wi_z = wi[li*3+1], wi_n = wi[li*3+2];
        const float wh_r = wh[li*3+0], wh_z = wh[li*3+1], wh_n = wh[li*3+2];
        const float bi_r = bi[li*3+0], bi_z = bi[li*3+1], bi_n = bi[li*3+2];
        const float bh_r = bh[li*3+0], bh_z = bh[li*3+1], bh_n = bh[li*3+2];
        hwi_r = 0.5f * wi_r; hwh_r = 0.5f * wh_r; hb_r = 0.5f * (bi_r + bh_r);
        hwi_z = 0.5f * wi_z; hwh_z = 0.5f * wh_z; hb_z = 0.5f * (bi_z + bh_z);
        wi_n_ = wi_n; bi_n_ = bi_n; hwh_n = 0.5f * wh_n; hbh_n = 0.5f * bh_n;
    };

    float a_hwi_r, a_hwh_r, a_hb_r, a_hwi_z, a_hwh_z, a_hb_z,
          a_wi_n, a_bi_n, a_hwh_n, a_hbh_n;
    float b_hwi_r, b_hwh_r, b_hb_r, b_hwi_z, b_hwh_z, b_hb_z,
          b_wi_n, b_bi_n, b_hwh_n, b_hbh_n;
    loadw(la, a_hwi_r, a_hwh_r, a_hb_r, a_hwi_z, a_hwh_z, a_hb_z,
              a_wi_n, a_bi_n, a_hwh_n, a_hbh_n);
    loadw(lb, b_hwi_r, b_hwh_r, b_hb_r, b_hwi_z, b_hwh_z, b_hb_z,
              b_wi_n, b_bi_n, b_hwh_n, b_hbh_n);

    // states + h-dependent precomputes (tail-updated, off the x-chain)
    float ha = 0.0f, hb_s = 0.0f;
    float a_ncr = a_hb_r, a_ncz = a_hb_z, a_ghn = a_hbh_n, a_hh = 0.0f;
    float b_ncr = b_hb_r, b_ncz = b_hb_z, b_ghn = b_hbh_n, b_hh = 0.0f;

    __syncthreads();

    const float* inbox  = (w == 0) ? xs : bb[w - 1];
    float*       outbox = (w < NW - 1) ? bb[w] : bb[0];
    const bool   is_prod = (lane == 31) && (w < NW - 1);
    const bool   is_last = (tid == 127);
    const unsigned rel_addr =
        (unsigned)__cvta_generic_to_shared(&rel_scratch[w]);

    #pragma unroll 1
    for (int ic = 0; ic < NCH; ++ic) {
        // consumer: wait for upstream chunk ic, prefetch 8 inbox values
        if (w > 0 && ic < GRU_T / KC) {
            asm volatile("bar.sync %0, %1;" :: "r"(w), "r"(64) : "memory");
        }
        float pf[KC];
        if (lane == 0 && ic < GRU_T / KC) {
            float4 va = *(const float4*)(inbox + ic * KC);
            float4 vb = *(const float4*)(inbox + ic * KC + 4);
            pf[0]=va.x; pf[1]=va.y; pf[2]=va.z; pf[3]=va.w;
            pf[4]=vb.x; pf[5]=vb.y; pf[6]=vb.z; pf[7]=vb.w;
        }

        #pragma unroll
        for (int u = 0; u < KC; ++u) {
            const int j = ic * KC + u;
            const int t = j - lane;
            const bool valid = (t >= 0) && (t < GRU_T);

            float x = __shfl_up_sync(0xFFFFFFFFu, hb_s, 1);
            if (lane == 0) x = pf[u];

            // ---- cell A (layer 2*tid), input x ----
            {
                const float t_r = ftanh(fmaf(a_hwi_r, x, a_ncr));
                const float t_z = ftanh(fmaf(a_hwi_z, x, a_ncz));
                const float xn  = fmaf(a_wi_n, x, a_bi_n);
                const float t_n = ftanh(fmaf(a_ghn, t_r, xn + a_ghn));
                const float A   = fmaf(-0.5f, t_z, 0.5f);
                const float C   = fmaf(a_hh, t_z, a_hh);
                const float hn  = fmaf(A, t_n, C);
                if (valid) ha = hn;
            }
            // ---- cell B (layer 2*tid+1), input ha ----
            {
                const float t_r = ftanh(fmaf(b_hwi_r, ha, b_ncr));
                const float t_z = ftanh(fmaf(b_hwi_z, ha, b_ncz));
                const float xn  = fmaf(b_wi_n, ha, b_bi_n);
                const float t_n = ftanh(fmaf(b_ghn, t_r, xn + b_ghn));
                const float A   = fmaf(-0.5f, t_z, 0.5f);
                const float C   = fmaf(b_hh, t_z, b_hh);
                const float hn  = fmaf(A, t_n, C);
                if (valid) hb_s = hn;
            }

            if (is_prod && valid) outbox[t] = hb_s;   // plain STS, off-chain

            // tails: next step's h-dependent terms (off the x-chain)
            a_ncr = fmaf(a_hwh_r, ha, a_hb_r);
            a_ncz = fmaf(a_hwh_z, ha, a_hb_z);
            a_ghn = fmaf(a_hwh_n, ha, a_hbh_n);
            a_hh  = 0.5f * ha;
            b_ncr = fmaf(b_hwh_r, hb_s, b_hb_r);
            b_ncz = fmaf(b_hwh_z, hb_s, b_hb_z);
            b_ghn = fmaf(b_hwh_n, hb_s, b_hbh_n);
            b_hh  = 0.5f * hb_s;

            if (is_last && valid) out[t] = hb_s;          // dec_out (layer 255)
            if (t == GRU_T - 1 && la >= 128) {            // dec_h
                out[GRU_T + (la - 128)] = ha;
                out[GRU_T + (lb - 128)] = hb_s;
            }
        }

        // producer: publish t-chunk ic-4 (complete at inner step 8*ic+6)
        if (w < NW - 1 && ic >= 4) {
            if (is_prod) {
                asm volatile("st.release.cta.shared.b32 [%0], %1;"
                             :: "r"(rel_addr), "r"(ic) : "memory");
            }
            asm volatile("bar.arrive %0, %1;" :: "r"(w + 1), "r"(64) : "memory");
        }
    }
}

extern "C" void kernel_launch(void* const* d_in, const int* in_sizes, int n_in,
                              void* d_out, int out_size)
{
    const float* X   = (const float*)d_in[0];
    const float* ewi = (const float*)d_in[1];
    const float* ewh = (const float*)d_in[2];
    const float* ebi = (const float*)d_in[3];
    const float* ebh = (const float*)d_in[4];
    const float* dwi = (const float*)d_in[5];
    const float* dwh = (const float*)d_in[6];
    const float* dbi = (const float*)d_in[7];
    const float* dbh = (const float*)d_in[8];
    float* out = (float*)d_out;

    gru_wave_v7<<<1, 128>>>(X, ewi, ewh, ebi, ebh, dwi, dwh, dbi, dbh, out);
}